// round 7
// baseline (speedup 1.0000x reference)
#include <cuda_runtime.h>
#include <cstdint>

#define N_   4
#define L_   4096
#define H_   8
#define D_   64
#define NH   32
#define EPSF 1e-6f

#define P1_CHUNKS 32
#define P1_LC (L_ / P1_CHUNKS)   // 128 tokens per pass1 CTA
#define P1_T  32                 // tokens per smem tile
#define P1_NT (P1_LC / P1_T)     // 4 tiles, 2-stage cp.async pipeline
#define NPART P1_CHUNKS

#define TL2 128                  // tokens per pass2 CTA
#define STR 68                   // padded row stride: 16B-aligned rows, conflict-free fragment reads

// Scratch (allocation-free rule: device globals)
__device__ float g_KVp[NH][NPART][D_ * D_];
__device__ float g_KSp[NH][NPART][D_];
__device__ float g_KV[NH][D_ * D_];
__device__ float g_KS[NH][D_];

__device__ __forceinline__ float fmap(float x) {      // elu(x)+1
    return x > 0.f ? x + 1.f : __expf(x);
}
__device__ __forceinline__ float totf32(float x) {    // round-to-nearest tf32
    uint32_t u;
    asm("cvt.rna.tf32.f32 %0, %1;" : "=r"(u) : "f"(x));
    return __uint_as_float(u);
}
__device__ __forceinline__ float ffrag(float x) { return totf32(fmap(x)); }

__device__ __forceinline__ void cp16(void* smem_dst, const void* gmem_src) {
    uint32_t d = (uint32_t)__cvta_generic_to_shared(smem_dst);
    asm volatile("cp.async.cg.shared.global [%0], [%1], 16;\n" :: "r"(d), "l"(gmem_src));
}
__device__ __forceinline__ void cp_commit() {
    asm volatile("cp.async.commit_group;\n");
}
template <int N>
__device__ __forceinline__ void cp_wait() {
    asm volatile("cp.async.wait_group %0;\n" :: "n"(N));
}

__device__ __forceinline__ void mma_tf32(float* c,
                                         uint32_t a0, uint32_t a1, uint32_t a2, uint32_t a3,
                                         uint32_t b0, uint32_t b1) {
    asm volatile("mma.sync.aligned.m16n8k8.row.col.f32.tf32.tf32.f32 "
                 "{%0,%1,%2,%3}, {%4,%5,%6,%7}, {%8,%9}, {%0,%1,%2,%3};\n"
                 : "+f"(c[0]), "+f"(c[1]), "+f"(c[2]), "+f"(c[3])
                 : "r"(a0), "r"(a1), "r"(a2), "r"(a3), "r"(b0), "r"(b1));
}

// ───────────────────────── Pass 1: KV[d][m] = Σ_l f(k)[l,d]·v[l,m], Ksum[d] = Σ_l f(k)[l,d]
// Grid (NH, 32), 256 threads. Warp w: d-tile (w>>1)*16, m-half (w&1)*32.
// cp.async double buffer; ONE vectorized fmap/rna convert stage per tile;
// MMA loop is pure LDS+MMA (no per-read cvt).
struct P1Smem {
    float ks[2][P1_T][STR];
    float vs[2][P1_T][STR];
};
#define SMEM1 ((int)sizeof(P1Smem))

__global__ __launch_bounds__(256) void pass1(const float* __restrict__ keys,
                                             const float* __restrict__ values) {
    extern __shared__ char smraw[];
    P1Smem& sm = *reinterpret_cast<P1Smem*>(smraw);

    const int nh = blockIdx.x, chunk = blockIdx.y;
    const int n = nh >> 3, h = nh & 7;
    const int tid = threadIdx.x;
    const int w = tid >> 5, lane = tid & 31;
    const int gid = lane >> 2, tig = lane & 3;
    const int d0 = (w >> 1) * 16;
    const int c0 = (w & 1) * 32;

    const float* kb = keys   + ((size_t)(n * L_) * H_ + h) * D_;
    const float* vb = values + ((size_t)(n * L_) * H_ + h) * D_;
    const int l0 = chunk * P1_LC;

    const int t0 = tid >> 4, q40 = (tid & 15) * 4;
    const int t1 = t0 + 16;

    auto issue = [&](int it) {
        const int b = it & 1;
        const int lb = l0 + it * P1_T;
        cp16(&sm.ks[b][t0][q40], kb + (size_t)(lb + t0) * (H_ * D_) + q40);
        cp16(&sm.vs[b][t0][q40], vb + (size_t)(lb + t0) * (H_ * D_) + q40);
        cp16(&sm.ks[b][t1][q40], kb + (size_t)(lb + t1) * (H_ * D_) + q40);
        cp16(&sm.vs[b][t1][q40], vb + (size_t)(lb + t1) * (H_ * D_) + q40);
        cp_commit();
    };

    float acc[4][4] = {};
    float s_lo = 0.f, s_hi = 0.f;

    issue(0);
    #pragma unroll
    for (int it = 0; it < P1_NT; ++it) {
        if (it + 1 < P1_NT) { issue(it + 1); cp_wait<1>(); }
        else                { cp_wait<0>(); }
        __syncthreads();

        float (*ksb)[STR] = sm.ks[it & 1];
        float (*vsb)[STR] = sm.vs[it & 1];

        // convert stage: each element exactly once, vectorized
        {
            float4* kp0 = (float4*)&ksb[t0][q40];
            float4* kp1 = (float4*)&ksb[t1][q40];
            float4* vp0 = (float4*)&vsb[t0][q40];
            float4* vp1 = (float4*)&vsb[t1][q40];
            float4 a = *kp0, b = *kp1, c = *vp0, d = *vp1;
            a.x = ffrag(a.x); a.y = ffrag(a.y); a.z = ffrag(a.z); a.w = ffrag(a.w);
            b.x = ffrag(b.x); b.y = ffrag(b.y); b.z = ffrag(b.z); b.w = ffrag(b.w);
            c.x = totf32(c.x); c.y = totf32(c.y); c.z = totf32(c.z); c.w = totf32(c.w);
            d.x = totf32(d.x); d.y = totf32(d.y); d.z = totf32(d.z); d.w = totf32(d.w);
            *kp0 = a; *kp1 = b; *vp0 = c; *vp1 = d;
        }
        __syncthreads();

        #pragma unroll
        for (int kk = 0; kk < P1_T; kk += 8) {
            float a0f = ksb[kk + tig    ][d0 + gid    ];
            float a1f = ksb[kk + tig    ][d0 + gid + 8];
            float a2f = ksb[kk + tig + 4][d0 + gid    ];
            float a3f = ksb[kk + tig + 4][d0 + gid + 8];
            s_lo += a0f + a2f;
            s_hi += a1f + a3f;
            uint32_t a0 = __float_as_uint(a0f), a1 = __float_as_uint(a1f);
            uint32_t a2 = __float_as_uint(a2f), a3 = __float_as_uint(a3f);
            #pragma unroll
            for (int j = 0; j < 4; ++j) {
                uint32_t b0 = __float_as_uint(vsb[kk + tig    ][c0 + j * 8 + gid]);
                uint32_t b1 = __float_as_uint(vsb[kk + tig + 4][c0 + j * 8 + gid]);
                mma_tf32(acc[j], a0, a1, a2, a3, b0, b1);
            }
        }
        __syncthreads();   // protect buffer reuse two iterations ahead
    }

    s_lo += __shfl_xor_sync(0xffffffffu, s_lo, 1);
    s_lo += __shfl_xor_sync(0xffffffffu, s_lo, 2);
    s_hi += __shfl_xor_sync(0xffffffffu, s_hi, 1);
    s_hi += __shfl_xor_sync(0xffffffffu, s_hi, 2);

    if (c0 == 0 && tig == 0) {
        g_KSp[nh][chunk][d0 + gid]     = s_lo;
        g_KSp[nh][chunk][d0 + gid + 8] = s_hi;
    }
    float* kv = g_KVp[nh][chunk];
    #pragma unroll
    for (int j = 0; j < 4; ++j) {
        int col = c0 + j * 8 + tig * 2;
        *(float2*)&kv[(d0 + gid    ) * D_ + col] = make_float2(acc[j][0], acc[j][1]);
        *(float2*)&kv[(d0 + gid + 8) * D_ + col] = make_float2(acc[j][2], acc[j][3]);
    }
}

// ───────────────────────── Reduce: sum 32 partials; pre-convert KV to tf32 for pass2
__global__ __launch_bounds__(256) void reduce_kernel() {
    if (blockIdx.x < 128) {
        int base = blockIdx.x * 256 + threadIdx.x;   // float4 index into [NH][4096]
        int nh = base >> 10;
        int e  = base & 1023;
        float4 s = make_float4(0.f, 0.f, 0.f, 0.f);
        #pragma unroll 8
        for (int p = 0; p < NPART; ++p) {
            float4 v = ((const float4*)g_KVp[nh][p])[e];
            s.x += v.x; s.y += v.y; s.z += v.z; s.w += v.w;
        }
        s.x = totf32(s.x); s.y = totf32(s.y); s.z = totf32(s.z); s.w = totf32(s.w);
        ((float4*)g_KV[nh])[e] = s;
    } else {
        for (int i = threadIdx.x; i < NH * D_ / 4; i += 256) {
            int nh = i >> 4;
            int e  = i & 15;
            float4 s = make_float4(0.f, 0.f, 0.f, 0.f);
            #pragma unroll 8
            for (int p = 0; p < NPART; ++p) {
                float4 v = ((const float4*)g_KSp[nh][p])[e];
                s.x += v.x; s.y += v.y; s.z += v.z; s.w += v.w;
            }
            ((float4*)g_KS[nh])[e] = s;
        }
    }
}

// ───────────────────────── Pass 2: out[l][m] = z_l · Σ_d f(q)[l,d]·KV[d][m]
// Grid (NH, 32), 512 threads. One cp.async burst, one vectorized q convert stage,
// pure LDS+MMA loop. 52.5KB smem.
struct P2Smem {
    float kv[D_][STR];
    float q[TL2][STR];
    float ks[D_];
};
#define SMEM2 ((int)sizeof(P2Smem))

__global__ __launch_bounds__(512) void pass2(const float* __restrict__ queries,
                                             float* __restrict__ out) {
    extern __shared__ char smraw[];
    P2Smem& sm = *reinterpret_cast<P2Smem*>(smraw);

    const int nh = blockIdx.x, tile = blockIdx.y;
    const int n = nh >> 3, h = nh & 7;
    const int tid = threadIdx.x;
    const int w = tid >> 5, lane = tid & 31;
    const int gid = lane >> 2, tig = lane & 3;
    const int l0 = tile * TL2;

    // q tile first (DRAM): 2048 16B chunks over 512 threads
    const float* qb = queries + ((size_t)(n * L_) * H_ + h) * D_;
    #pragma unroll
    for (int r = 0; r < 4; ++r) {
        int f = r * 512 + tid;
        int t = f >> 4, q4 = (f & 15) * 4;
        cp16(&sm.q[t][q4], qb + (size_t)(l0 + t) * (H_ * D_) + q4);
    }
    // KV tile (L2-resident, already tf32): 1024 chunks
    #pragma unroll
    for (int r = 0; r < 2; ++r) {
        int f = r * 512 + tid;
        int dd = f >> 4, q4 = (f & 15) * 4;
        cp16(&sm.kv[dd][q4], (const char*)g_KV[nh] + (size_t)f * 16);
    }
    if (tid < D_) sm.ks[tid] = g_KS[nh][tid];
    cp_commit();
    cp_wait<0>();
    __syncthreads();

    // convert q once, vectorized: 4 float4 per thread
    #pragma unroll
    for (int r = 0; r < 4; ++r) {
        int f = r * 512 + tid;
        int t = f >> 4, q4 = (f & 15) * 4;
        float4* p = (float4*)&sm.q[t][q4];
        float4 a = *p;
        a.x = ffrag(a.x); a.y = ffrag(a.y); a.z = ffrag(a.z); a.w = ffrag(a.w);
        *p = a;
    }
    __syncthreads();

    const int lb = (w >> 1) * 16;
    const int c0 = (w & 1) * 32;
    float acc[4][4] = {};
    float s_lo = 0.f, s_hi = 0.f;

    #pragma unroll
    for (int kk = 0; kk < D_; kk += 8) {
        float ka = sm.ks[kk + tig], kc = sm.ks[kk + tig + 4];
        float a0f = sm.q[lb + gid    ][kk + tig    ];
        float a1f = sm.q[lb + gid + 8][kk + tig    ];
        float a2f = sm.q[lb + gid    ][kk + tig + 4];
        float a3f = sm.q[lb + gid + 8][kk + tig + 4];
        s_lo += a0f * ka + a2f * kc;
        s_hi += a1f * ka + a3f * kc;
        uint32_t a0 = __float_as_uint(a0f), a1 = __float_as_uint(a1f);
        uint32_t a2 = __float_as_uint(a2f), a3 = __float_as_uint(a3f);
        #pragma unroll
        for (int j = 0; j < 4; ++j) {
            uint32_t b0 = __float_as_uint(sm.kv[kk + tig    ][c0 + j * 8 + gid]);
            uint32_t b1 = __float_as_uint(sm.kv[kk + tig + 4][c0 + j * 8 + gid]);
            mma_tf32(acc[j], a0, a1, a2, a3, b0, b1);
        }
    }

    s_lo += __shfl_xor_sync(0xffffffffu, s_lo, 1);
    s_lo += __shfl_xor_sync(0xffffffffu, s_lo, 2);
    s_hi += __shfl_xor_sync(0xffffffffu, s_hi, 1);
    s_hi += __shfl_xor_sync(0xffffffffu, s_hi, 2);
    const float z_lo = 1.f / (s_lo + EPSF);
    const float z_hi = 1.f / (s_hi + EPSF);

    float* ob_lo = out + (((size_t)(n * L_) + l0 + lb + gid    ) * H_ + h) * D_ + c0;
    float* ob_hi = out + (((size_t)(n * L_) + l0 + lb + gid + 8) * H_ + h) * D_ + c0;
    #pragma unroll
    for (int j = 0; j < 4; ++j) {
        int col = j * 8 + tig * 2;
        *(float2*)(ob_lo + col) = make_float2(acc[j][0] * z_lo, acc[j][1] * z_lo);
        *(float2*)(ob_hi + col) = make_float2(acc[j][2] * z_hi, acc[j][3] * z_hi);
    }
}

extern "C" void kernel_launch(void* const* d_in, const int* in_sizes, int n_in,
                              void* d_out, int out_size) {
    const float* q = (const float*)d_in[0];
    const float* k = (const float*)d_in[1];
    const float* v = (const float*)d_in[2];
    float* out = (float*)d_out;
    (void)in_sizes; (void)n_in; (void)out_size;

    // Idempotent, not stream ops — safe under graph capture.
    cudaFuncSetAttribute(pass1, cudaFuncAttributeMaxDynamicSharedMemorySize, SMEM1);
    cudaFuncSetAttribute(pass2, cudaFuncAttributeMaxDynamicSharedMemorySize, SMEM2);

    pass1<<<dim3(NH, P1_CHUNKS), 256, SMEM1>>>(k, v);
    reduce_kernel<<<129, 256>>>();
    pass2<<<dim3(NH, L_ / TL2), 512, SMEM2>>>(q, out);
}